// round 7
// baseline (speedup 1.0000x reference)
#include <cuda_runtime.h>

#define IN_CH 10
#define UNITS 32
#define PILLARS 30000
#define NPAR (UNITS * IN_CH + 2 * UNITS)
#define NMOM 65  /* 10 first moments + 55 unique second moments */
#define PAD 36   /* floats per point-row in smem: 144B, 16B-aligned */

// ---------------- device-global scratch (no runtime allocation) ----------------
__constant__ float c_W[UNITS * IN_CH];   // raw W (stats/finalize)
__constant__ float c_P[NPAR];            // W'(320) | shift(32) | prelu(32)

__device__ double   g_acc[NMOM + 7];
__device__ float    g_params[NPAR];
__device__ float    g_psum[PILLARS * UNITS];
__device__ unsigned g_pmax[PILLARS * UNITS];   // fkey-encoded, init 0
__device__ float    g_cnt[PILLARS];
__device__ float    g_hybrid[PILLARS * UNITS];

// ---------------- helpers ----------------
__device__ __forceinline__ unsigned fkey(float f) {
    unsigned u = __float_as_uint(f);
    return (u & 0x80000000u) ? ~u : (u | 0x80000000u);
}
__device__ __forceinline__ float finv(unsigned u) {
    return __uint_as_float((u & 0x80000000u) ? (u & 0x7fffffffu) : ~u);
}
__device__ __forceinline__ void red_add_v4(float* addr, float4 v) {
    asm volatile("red.global.add.v4.f32 [%0], {%1, %2, %3, %4};"
                 :: "l"(addr), "f"(v.x), "f"(v.y), "f"(v.z), "f"(v.w) : "memory");
}
__device__ __forceinline__ void red_max_u32(unsigned* addr, unsigned v) {
    asm volatile("red.global.max.u32 [%0], %1;" :: "l"(addr), "r"(v) : "memory");
}
__device__ __forceinline__ void red_add_f32(float* addr, float v) {
    asm volatile("red.global.add.f32 [%0], %1;" :: "l"(addr), "f"(v) : "memory");
}

// ---------------- K0: zero/init accumulators ----------------
__global__ void k_init() {
    int i = blockIdx.x * blockDim.x + threadIdx.x;
    int stride = gridDim.x * blockDim.x;
    float4 z4 = make_float4(0.f, 0.f, 0.f, 0.f);
    uint4  zu = make_uint4(0u, 0u, 0u, 0u);
    for (int j = i; j < PILLARS * UNITS / 4; j += stride) {
        ((float4*)g_psum)[j] = z4;
        ((uint4*)g_pmax)[j] = zu;
    }
    for (int j = i; j < PILLARS / 4; j += stride) ((float4*)g_cnt)[j] = z4;
    if (i < NMOM) g_acc[i] = 0.0;
}

// ---------------- K1: input moments (Σr, Σ r_i r_j), paired float4 loads ----------------
__global__ void __launch_bounds__(256) k_stats(const float* __restrict__ in, long long n) {
    float s[IN_CH];
    float m[55];
#pragma unroll
    for (int k = 0; k < IN_CH; k++) s[k] = 0.0f;
#pragma unroll
    for (int k = 0; k < 55; k++) m[k] = 0.0f;

    long long i0 = (long long)blockIdx.x * blockDim.x + threadIdx.x;
    long long stride = (long long)gridDim.x * blockDim.x;
    long long npair = n >> 1;
    for (long long p2 = i0; p2 < npair; p2 += stride) {
        const float4* q = (const float4*)(in + p2 * 2 * IN_CH);
        float4 a = __ldg(q + 0), b = __ldg(q + 1), c = __ldg(q + 2),
               d = __ldg(q + 3), e = __ldg(q + 4);
        float r0[IN_CH] = {a.x, a.y, a.z, a.w, b.x, b.y, b.z, b.w, c.x, c.y};
        float r1[IN_CH] = {c.z, c.w, d.x, d.y, d.z, d.w, e.x, e.y, e.z, e.w};
        int idx = 0;
#pragma unroll
        for (int i = 0; i < IN_CH; i++) {
            s[i] += r0[i] + r1[i];
#pragma unroll
            for (int j = 0; j <= i; j++) {
                m[idx] = fmaf(r0[i], r0[j], m[idx]);
                m[idx] = fmaf(r1[i], r1[j], m[idx]);
                idx++;
            }
        }
    }
    // odd tail
    if (i0 == 0 && (n & 1)) {
        const float* row = in + (n - 1) * IN_CH;
        float r[IN_CH];
#pragma unroll
        for (int k = 0; k < IN_CH; k++) r[k] = row[k];
        int idx = 0;
#pragma unroll
        for (int i = 0; i < IN_CH; i++) {
            s[i] += r[i];
#pragma unroll
            for (int j = 0; j <= i; j++) { m[idx] = fmaf(r[i], r[j], m[idx]); idx++; }
        }
    }

    // warp reduce
#pragma unroll
    for (int k = 0; k < IN_CH; k++)
#pragma unroll
        for (int off = 16; off; off >>= 1) s[k] += __shfl_down_sync(0xffffffffu, s[k], off);
#pragma unroll
    for (int k = 0; k < 55; k++)
#pragma unroll
        for (int off = 16; off; off >>= 1) m[k] += __shfl_down_sync(0xffffffffu, m[k], off);

    __shared__ double sh[NMOM];
    int tid = threadIdx.x;
    for (int k = tid; k < NMOM; k += blockDim.x) sh[k] = 0.0;
    __syncthreads();
    if ((tid & 31) == 0) {
#pragma unroll
        for (int k = 0; k < IN_CH; k++) atomicAdd(&sh[k], (double)s[k]);
#pragma unroll
        for (int k = 0; k < 55; k++) atomicAdd(&sh[IN_CH + k], (double)m[k]);
    }
    __syncthreads();
    for (int k = tid; k < NMOM; k += blockDim.x) atomicAdd(&g_acc[k], sh[k]);
}

// ---------------- K2: fold BN into weights ----------------
__global__ void k_finalize(const float* __restrict__ gamma,
                           const float* __restrict__ beta,
                           const float* __restrict__ prelu,
                           long long n) {
    int c = threadIdx.x;  // launched with 32 threads
    if (c >= UNITS) return;
    double invn = 1.0 / (double)n;
    double wr[IN_CH];
    double mean = 0.0;
#pragma unroll
    for (int k = 0; k < IN_CH; k++) {
        wr[k] = (double)c_W[c * IN_CH + k];
        mean += wr[k] * g_acc[k];
    }
    mean *= invn;
    double e2 = 0.0;
    int idx = 0;
#pragma unroll
    for (int i = 0; i < IN_CH; i++)
#pragma unroll
        for (int j = 0; j <= i; j++) {
            double t = wr[i] * wr[j] * g_acc[IN_CH + idx];
            idx++;
            e2 += (i == j) ? t : 2.0 * t;
        }
    e2 *= invn;
    double var = e2 - mean * mean;
    double rstd = 1.0 / sqrt(var + 1e-3);
    float scale = gamma[c] * (float)rstd;
#pragma unroll
    for (int k = 0; k < IN_CH; k++) g_params[c * IN_CH + k] = c_W[c * IN_CH + k] * scale;
    g_params[UNITS * IN_CH + c]         = beta[c] - (float)mean * scale;
    g_params[UNITS * IN_CH + UNITS + c] = prelu[c];
}

// ---------------- K3: GEMV + PReLU; single merged pass (scalar u32 max + v4 sum + store + count) ----------------
__global__ void __launch_bounds__(256, 6) k_main(const float* __restrict__ in,
                                                 const int* __restrict__ inv,
                                                 float* __restrict__ out,
                                                 long long n) {
    __shared__ float sy[8 * 32 * PAD];
    const int lane = threadIdx.x & 31;
    const int w = threadIdx.x >> 5;
    const int jq = lane >> 3;          // point-in-quad
    const int c4 = (lane & 7) << 2;    // channel group base
    float* my = sy + w * 32 * PAD;

    long long gw = (long long)blockIdx.x * 8 + w;
    long long nwarps = (long long)gridDim.x * 8;

    for (long long base = gw * 32; base < n; base += nwarps * 32) {
        long long p = base + lane;
        int pid = 0;
        if (p < n) {
            const float* row = in + p * IN_CH;
            float r[IN_CH];
#pragma unroll
            for (int k = 0; k < IN_CH; k++) r[k] = __ldg(row + k);
            pid = __ldg(inv + p);
            float4* dst = (float4*)(my + lane * PAD);
#pragma unroll
            for (int g = 0; g < 8; g++) {
                float4 v;
#pragma unroll
                for (int e = 0; e < 4; e++) {
                    int c = g * 4 + e;
                    float x = c_P[UNITS * IN_CH + c];
#pragma unroll
                    for (int k = 0; k < IN_CH; k++) x = fmaf(r[k], c_P[c * IN_CH + k], x);
                    ((float*)&v)[e] = (x > 0.0f) ? x : c_P[UNITS * IN_CH + UNITS + c] * x;
                }
                dst[g] = v;
            }
        }
        __syncwarp();

        // merged pass: 4 points per iteration, lane = (point-in-quad, channel-group)
#pragma unroll
        for (int it = 0; it < 8; it++) {
            int j = it * 4 + jq;
            unsigned pj = (unsigned)__shfl_sync(0xffffffffu, pid, j);
            long long pp = base + j;
            if (pp < n) {
                float4 v = *(float4*)(my + j * PAD + c4);
                unsigned* mx = g_pmax + (pj << 5) + c4;
                red_max_u32(mx + 0, fkey(v.x));
                red_max_u32(mx + 1, fkey(v.y));
                red_max_u32(mx + 2, fkey(v.z));
                red_max_u32(mx + 3, fkey(v.w));
                red_add_v4(g_psum + (pj << 5) + c4, v);
                *(float4*)(out + (size_t)pp * 64 + c4) = v;
                if ((lane & 7) == 0) red_add_f32(&g_cnt[pj], 1.0f);
            }
        }
        __syncwarp();
    }
}

// ---------------- K4: per-pillar hybrid feature (vectorized) ----------------
__global__ void k_hybrid(const float* __restrict__ alpha) {
    float a = 1.0f / (1.0f + __expf(-alpha[0]));
    int i = blockIdx.x * blockDim.x + threadIdx.x;
    int stride = gridDim.x * blockDim.x;
    for (int j4 = i; j4 < PILLARS * UNITS / 4; j4 += stride) {
        int pid = j4 >> 3;
        float cnt = g_cnt[pid];
        float4 sm = ((float4*)g_psum)[j4];
        uint4 mu = ((uint4*)g_pmax)[j4];
        float rc = 1.0f / fmaxf(cnt, 1.0f);
        bool has = (cnt > 0.0f);
        float4 h;
        h.x = a * (has ? finv(mu.x) : 0.0f) + (1.0f - a) * sm.x * rc;
        h.y = a * (has ? finv(mu.y) : 0.0f) + (1.0f - a) * sm.y * rc;
        h.z = a * (has ? finv(mu.z) : 0.0f) + (1.0f - a) * sm.z * rc;
        h.w = a * (has ? finv(mu.w) : 0.0f) + (1.0f - a) * sm.w * rc;
        ((float4*)g_hybrid)[j4] = h;
    }
}

// ---------------- K5: gather hybrid into right half (vectorized transposed) ----------------
__global__ void __launch_bounds__(256) k_gather(const int* __restrict__ inv,
                                                float* __restrict__ out,
                                                long long n) {
    const int lane = threadIdx.x & 31;
    const int w = threadIdx.x >> 5;
    const int jq = lane >> 3;
    const int c4 = (lane & 7) << 2;
    long long gw = (long long)blockIdx.x * 8 + w;
    long long nwarps = (long long)gridDim.x * 8;

    for (long long base = gw * 32; base < n; base += nwarps * 32) {
        long long p = base + lane;
        int pid = (p < n) ? __ldg(inv + p) : 0;
#pragma unroll
        for (int it = 0; it < 8; it++) {
            int j = it * 4 + jq;
            unsigned pj = (unsigned)__shfl_sync(0xffffffffu, pid, j);
            long long pp = base + j;
            if (pp < n) {
                float4 v = __ldg((const float4*)(g_hybrid + (pj << 5) + c4));
                *(float4*)(out + (size_t)pp * 64 + 32 + c4) = v;
            }
        }
    }
}

// ---------------- launch ----------------
extern "C" void kernel_launch(void* const* d_in, const int* in_sizes, int n_in,
                              void* d_out, int out_size) {
    const float* inputs = (const float*)d_in[0];
    const float* W      = (const float*)d_in[1];
    const float* gamma  = (const float*)d_in[2];
    const float* beta   = (const float*)d_in[3];
    const float* prelu  = (const float*)d_in[4];
    const float* alpha  = (const float*)d_in[5];
    const int*   inv    = (const int*)d_in[6];
    long long n = (long long)in_sizes[0] / IN_CH;
    float* out = (float*)d_out;

    void *pW = 0, *pP = 0, *pPar = 0;
    cudaGetSymbolAddress(&pW, c_W);
    cudaGetSymbolAddress(&pP, c_P);
    cudaGetSymbolAddress(&pPar, g_params);

    cudaMemcpyAsync(pW, W, UNITS * IN_CH * sizeof(float), cudaMemcpyDeviceToDevice, 0);

    k_init<<<512, 256>>>();
    k_stats<<<592, 256>>>(inputs, n);
    k_finalize<<<1, 32>>>(gamma, beta, prelu, n);

    cudaMemcpyAsync(pP, pPar, NPAR * sizeof(float), cudaMemcpyDeviceToDevice, 0);

    k_main<<<2048, 256>>>(inputs, inv, out, n);
    k_hybrid<<<512, 256>>>(alpha);
    k_gather<<<2048, 256>>>(inv, out, n);
}

// round 8
// speedup vs baseline: 1.4985x; 1.4985x over previous
#include <cuda_runtime.h>

#define IN_CH 10
#define UNITS 32
#define PILLARS 30000
#define NPAR (UNITS * IN_CH + 2 * UNITS)
#define NMOM 65  /* 10 first moments + 55 unique second moments */
#define PAD 36   /* floats per point-row in smem: 144B, 16B-aligned */

// ---------------- device-global scratch (no runtime allocation) ----------------
__constant__ float c_P[NPAR];            // W'(320) | shift(32) | prelu(32)

__device__ double   g_acc[NMOM + 7];
__device__ float    g_params[NPAR];
__device__ float    g_psum[PILLARS * UNITS];
__device__ unsigned g_pmax[PILLARS * UNITS];   // fkey-encoded, init 0
__device__ float    g_cnt[PILLARS];
__device__ float    g_hybrid[PILLARS * UNITS];

// ---------------- helpers ----------------
__device__ __forceinline__ unsigned fkey(float f) {
    unsigned u = __float_as_uint(f);
    return (u & 0x80000000u) ? ~u : (u | 0x80000000u);
}
__device__ __forceinline__ float finv(unsigned u) {
    return __uint_as_float((u & 0x80000000u) ? (u & 0x7fffffffu) : ~u);
}
__device__ __forceinline__ void red_add_v4(float* addr, float4 v) {
    asm volatile("red.global.add.v4.f32 [%0], {%1, %2, %3, %4};"
                 :: "l"(addr), "f"(v.x), "f"(v.y), "f"(v.z), "f"(v.w) : "memory");
}
__device__ __forceinline__ void red_max_u32(unsigned* addr, unsigned v) {
    asm volatile("red.global.max.u32 [%0], %1;" :: "l"(addr), "r"(v) : "memory");
}
__device__ __forceinline__ void red_add_f32(float* addr, float v) {
    asm volatile("red.global.add.f32 [%0], %1;" :: "l"(addr), "f"(v) : "memory");
}

// ---------------- K0: zero moment accumulators (must precede k_stats' atomics) ----------------
__global__ void k_init() {
    int i = threadIdx.x;
    if (i < NMOM) g_acc[i] = 0.0;
}

// ---------------- K1: zero pillar tables + input moments (Σr, Σ r_i r_j) ----------------
__global__ void __launch_bounds__(256) k_stats(const float* __restrict__ in, long long n) {
    // zero pillar accumulators (consumed by k_main, which launches later)
    {
        int i = blockIdx.x * blockDim.x + threadIdx.x;
        int stride = gridDim.x * blockDim.x;
        float4 z4 = make_float4(0.f, 0.f, 0.f, 0.f);
        uint4  zu = make_uint4(0u, 0u, 0u, 0u);
        for (int j = i; j < PILLARS * UNITS / 4; j += stride) {
            ((float4*)g_psum)[j] = z4;
            ((uint4*)g_pmax)[j] = zu;
        }
        for (int j = i; j < PILLARS / 4; j += stride) ((float4*)g_cnt)[j] = z4;
    }

    float s[IN_CH];
    float m[55];
#pragma unroll
    for (int k = 0; k < IN_CH; k++) s[k] = 0.0f;
#pragma unroll
    for (int k = 0; k < 55; k++) m[k] = 0.0f;

    long long i0 = (long long)blockIdx.x * blockDim.x + threadIdx.x;
    long long stride = (long long)gridDim.x * blockDim.x;
    long long npair = n >> 1;
    for (long long p2 = i0; p2 < npair; p2 += stride) {
        const float4* q = (const float4*)(in + p2 * 2 * IN_CH);
        float4 a = __ldg(q + 0), b = __ldg(q + 1), c = __ldg(q + 2),
               d = __ldg(q + 3), e = __ldg(q + 4);
        float r0[IN_CH] = {a.x, a.y, a.z, a.w, b.x, b.y, b.z, b.w, c.x, c.y};
        float r1[IN_CH] = {c.z, c.w, d.x, d.y, d.z, d.w, e.x, e.y, e.z, e.w};
        int idx = 0;
#pragma unroll
        for (int i = 0; i < IN_CH; i++) {
            s[i] += r0[i] + r1[i];
#pragma unroll
            for (int j = 0; j <= i; j++) {
                m[idx] = fmaf(r0[i], r0[j], m[idx]);
                m[idx] = fmaf(r1[i], r1[j], m[idx]);
                idx++;
            }
        }
    }
    // odd tail
    if (i0 == 0 && (n & 1)) {
        const float* row = in + (n - 1) * IN_CH;
        float r[IN_CH];
#pragma unroll
        for (int k = 0; k < IN_CH; k++) r[k] = row[k];
        int idx = 0;
#pragma unroll
        for (int i = 0; i < IN_CH; i++) {
            s[i] += r[i];
#pragma unroll
            for (int j = 0; j <= i; j++) { m[idx] = fmaf(r[i], r[j], m[idx]); idx++; }
        }
    }

    // warp reduce
#pragma unroll
    for (int k = 0; k < IN_CH; k++)
#pragma unroll
        for (int off = 16; off; off >>= 1) s[k] += __shfl_down_sync(0xffffffffu, s[k], off);
#pragma unroll
    for (int k = 0; k < 55; k++)
#pragma unroll
        for (int off = 16; off; off >>= 1) m[k] += __shfl_down_sync(0xffffffffu, m[k], off);

    __shared__ double sh[NMOM];
    int tid = threadIdx.x;
    for (int k = tid; k < NMOM; k += blockDim.x) sh[k] = 0.0;
    __syncthreads();
    if ((tid & 31) == 0) {
#pragma unroll
        for (int k = 0; k < IN_CH; k++) atomicAdd(&sh[k], (double)s[k]);
#pragma unroll
        for (int k = 0; k < 55; k++) atomicAdd(&sh[IN_CH + k], (double)m[k]);
    }
    __syncthreads();
    for (int k = tid; k < NMOM; k += blockDim.x) atomicAdd(&g_acc[k], sh[k]);
}

// ---------------- K2: fold BN into weights (reads raw W from global) ----------------
__global__ void k_finalize(const float* __restrict__ W,
                           const float* __restrict__ gamma,
                           const float* __restrict__ beta,
                           const float* __restrict__ prelu,
                           long long n) {
    int c = threadIdx.x;  // launched with 32 threads
    if (c >= UNITS) return;
    double invn = 1.0 / (double)n;
    double wr[IN_CH];
    double mean = 0.0;
#pragma unroll
    for (int k = 0; k < IN_CH; k++) {
        wr[k] = (double)W[c * IN_CH + k];
        mean += wr[k] * g_acc[k];
    }
    mean *= invn;
    double e2 = 0.0;
    int idx = 0;
#pragma unroll
    for (int i = 0; i < IN_CH; i++)
#pragma unroll
        for (int j = 0; j <= i; j++) {
            double t = wr[i] * wr[j] * g_acc[IN_CH + idx];
            idx++;
            e2 += (i == j) ? t : 2.0 * t;
        }
    e2 *= invn;
    double var = e2 - mean * mean;
    double rstd = 1.0 / sqrt(var + 1e-3);
    float scale = gamma[c] * (float)rstd;
#pragma unroll
    for (int k = 0; k < IN_CH; k++) g_params[c * IN_CH + k] = W[c * IN_CH + k] * scale;
    g_params[UNITS * IN_CH + c]         = beta[c] - (float)mean * scale;
    g_params[UNITS * IN_CH + UNITS + c] = prelu[c];
}

// ---------------- K3: staged loads; GEMV + PReLU; coalesced max pass; v4 sum pass ----------------
__global__ void __launch_bounds__(256, 6) k_main(const float* __restrict__ in,
                                                 const int* __restrict__ inv,
                                                 float* __restrict__ out,
                                                 long long n) {
    __shared__ float sy[8 * 32 * PAD];
    const int lane = threadIdx.x & 31;
    const int w = threadIdx.x >> 5;
    const int jq = lane >> 3;          // point-in-quad
    const int c4 = (lane & 7) << 2;    // channel group base
    float* my = sy + w * 32 * PAD;

    long long gw = (long long)blockIdx.x * 8 + w;
    long long nwarps = (long long)gridDim.x * 8;

    for (long long base = gw * 32; base < n; base += nwarps * 32) {
        int nv = (int)min((long long)32, n - base);
        int pid = 0;
        float r[IN_CH];

        if (nv == 32) {
            // warp-cooperative staged input load: 32 pts * 40B = 1280B = 80 float4
            const float4* src = (const float4*)(in + base * IN_CH);
            float4* st = (float4*)my;
            st[lane]      = __ldg(src + lane);
            st[lane + 32] = __ldg(src + lane + 32);
            if (lane < 16) st[lane + 64] = __ldg(src + lane + 64);
            __syncwarp();
#pragma unroll
            for (int i = 0; i < 5; i++) {
                float2 t = *(float2*)(my + lane * IN_CH + 2 * i);
                r[2 * i] = t.x;
                r[2 * i + 1] = t.y;
            }
            __syncwarp();
        } else if (lane < nv) {
#pragma unroll
            for (int k = 0; k < IN_CH; k++) r[k] = __ldg(in + (base + lane) * IN_CH + k);
        }
        if (lane < nv) {
            pid = __ldg(inv + base + lane);
            float4* dst = (float4*)(my + lane * PAD);
#pragma unroll
            for (int g = 0; g < 8; g++) {
                float4 v;
#pragma unroll
                for (int e = 0; e < 4; e++) {
                    int c = g * 4 + e;
                    float x = c_P[UNITS * IN_CH + c];
#pragma unroll
                    for (int k = 0; k < IN_CH; k++) x = fmaf(r[k], c_P[c * IN_CH + k], x);
                    ((float*)&v)[e] = (x > 0.0f) ? x : c_P[UNITS * IN_CH + UNITS + c] * x;
                }
                dst[g] = v;
            }
        }
        __syncwarp();

        if (nv == 32) {
            // pass 1: coalesced scalar max, lane = channel (one 128B line per RED)
#pragma unroll
            for (int j = 0; j < 32; j++) {
                unsigned pj = (unsigned)__shfl_sync(0xffffffffu, pid, j);
                float v = my[j * PAD + lane];
                red_max_u32(g_pmax + (pj << 5) + lane, fkey(v));
            }
            // pass 2: v4 sum + STG.128 left half + counts; 4 points per iteration
#pragma unroll
            for (int it = 0; it < 8; it++) {
                int j = it * 4 + jq;
                unsigned pj = (unsigned)__shfl_sync(0xffffffffu, pid, j);
                float4 v = *(float4*)(my + j * PAD + c4);
                red_add_v4(g_psum + (pj << 5) + c4, v);
                *(float4*)(out + (size_t)(base + j) * 64 + c4) = v;
                if ((lane & 7) == 0) red_add_f32(&g_cnt[pj], 1.0f);
            }
        } else {
            for (int j = 0; j < nv; j++) {
                unsigned pj = (unsigned)__shfl_sync(0xffffffffu, pid, j);
                float v = my[j * PAD + lane];
                red_max_u32(g_pmax + (pj << 5) + lane, fkey(v));
                atomicAdd(g_psum + (pj << 5) + lane, v);
                out[(size_t)(base + j) * 64 + lane] = v;
                if (lane == 0) red_add_f32(&g_cnt[pj], 1.0f);
            }
        }
        __syncwarp();
    }
}

// ---------------- K4: per-pillar hybrid feature (vectorized) ----------------
__global__ void k_hybrid(const float* __restrict__ alpha) {
    float a = 1.0f / (1.0f + __expf(-alpha[0]));
    int i = blockIdx.x * blockDim.x + threadIdx.x;
    int stride = gridDim.x * blockDim.x;
    for (int j4 = i; j4 < PILLARS * UNITS / 4; j4 += stride) {
        int pid = j4 >> 3;
        float cnt = g_cnt[pid];
        float4 sm = ((float4*)g_psum)[j4];
        uint4 mu = ((uint4*)g_pmax)[j4];
        float rc = 1.0f / fmaxf(cnt, 1.0f);
        bool has = (cnt > 0.0f);
        float4 h;
        h.x = a * (has ? finv(mu.x) : 0.0f) + (1.0f - a) * sm.x * rc;
        h.y = a * (has ? finv(mu.y) : 0.0f) + (1.0f - a) * sm.y * rc;
        h.z = a * (has ? finv(mu.z) : 0.0f) + (1.0f - a) * sm.z * rc;
        h.w = a * (has ? finv(mu.w) : 0.0f) + (1.0f - a) * sm.w * rc;
        ((float4*)g_hybrid)[j4] = h;
    }
}

// ---------------- K5: gather hybrid into right half (vectorized transposed) ----------------
__global__ void __launch_bounds__(256) k_gather(const int* __restrict__ inv,
                                                float* __restrict__ out,
                                                long long n) {
    const int lane = threadIdx.x & 31;
    const int w = threadIdx.x >> 5;
    const int jq = lane >> 3;
    const int c4 = (lane & 7) << 2;
    long long gw = (long long)blockIdx.x * 8 + w;
    long long nwarps = (long long)gridDim.x * 8;

    for (long long base = gw * 32; base < n; base += nwarps * 32) {
        long long p = base + lane;
        int pid = (p < n) ? __ldg(inv + p) : 0;
#pragma unroll
        for (int it = 0; it < 8; it++) {
            int j = it * 4 + jq;
            unsigned pj = (unsigned)__shfl_sync(0xffffffffu, pid, j);
            long long pp = base + j;
            if (pp < n) {
                float4 v = __ldg((const float4*)(g_hybrid + (pj << 5) + c4));
                *(float4*)(out + (size_t)pp * 64 + 32 + c4) = v;
            }
        }
    }
}

// ---------------- launch ----------------
extern "C" void kernel_launch(void* const* d_in, const int* in_sizes, int n_in,
                              void* d_out, int out_size) {
    const float* inputs = (const float*)d_in[0];
    const float* W      = (const float*)d_in[1];
    const float* gamma  = (const float*)d_in[2];
    const float* beta   = (const float*)d_in[3];
    const float* prelu  = (const float*)d_in[4];
    const float* alpha  = (const float*)d_in[5];
    const int*   inv    = (const int*)d_in[6];
    long long n = (long long)in_sizes[0] / IN_CH;
    float* out = (float*)d_out;

    void *pP = 0, *pPar = 0;
    cudaGetSymbolAddress(&pP, c_P);
    cudaGetSymbolAddress(&pPar, g_params);

    k_init<<<1, 128>>>();
    k_stats<<<592, 256>>>(inputs, n);
    k_finalize<<<1, 32>>>(W, gamma, beta, prelu, n);

    cudaMemcpyAsync(pP, pPar, NPAR * sizeof(float), cudaMemcpyDeviceToDevice, 0);

    k_main<<<2048, 256>>>(inputs, inv, out, n);
    k_hybrid<<<512, 256>>>(alpha);
    k_gather<<<2048, 256>>>(inv, out, n);
}